// round 1
// baseline (speedup 1.0000x reference)
#include <cuda_runtime.h>
#include <math.h>

#define BB     512
#define NN     4096
#define DD     128
#define HH     8
#define TPREV  2048
#define NW     8       // warps per CTA
#define NT     256

__device__ __forceinline__ float warpReduceSum(float v) {
#pragma unroll
    for (int o = 16; o > 0; o >>= 1) v += __shfl_xor_sync(0xffffffffu, v, o);
    return v;
}

// out[j] = sum_i x[i]*W[j*128+i] + bias[j], j in [0,128). All 256 threads.
// Caller must __syncthreads() before (x stable) and after (out ready).
__device__ void gemv128(const float* __restrict__ W, const float* __restrict__ bias,
                        const float* __restrict__ x, float* __restrict__ out, int tid)
{
    int warp = tid >> 5, lane = tid & 31;
    float4 xv = ((const float4*)x)[lane];
#pragma unroll
    for (int jj = 0; jj < 16; jj++) {
        int j = warp * 16 + jj;
        float4 wv = ((const float4*)(W + j * DD))[lane];
        float p = wv.x * xv.x + wv.y * xv.y + wv.z * xv.z + wv.w * xv.w;
        p = warpReduceSum(p);
        if (lane == 0) out[j] = p + bias[j];
    }
}

// In-place LayerNorm over 128 elements, done by warp 0.
// Caller must __syncthreads() before and after.
__device__ void layernorm128(float* __restrict__ x, const float* __restrict__ g,
                             const float* __restrict__ bb, int tid)
{
    if (tid < 32) {
        float v0 = x[tid], v1 = x[tid + 32], v2 = x[tid + 64], v3 = x[tid + 96];
        float s = warpReduceSum(v0 + v1 + v2 + v3);
        float mu = s * (1.0f / 128.0f);
        float d0 = v0 - mu, d1 = v1 - mu, d2 = v2 - mu, d3 = v3 - mu;
        float sq = warpReduceSum(d0 * d0 + d1 * d1 + d2 * d2 + d3 * d3);
        float rstd = rsqrtf(sq * (1.0f / 128.0f) + 1e-5f);
        x[tid]      = d0 * rstd * g[tid]      + bb[tid];
        x[tid + 32] = d1 * rstd * g[tid + 32] + bb[tid + 32];
        x[tid + 64] = d2 * rstd * g[tid + 64] + bb[tid + 64];
        x[tid + 96] = d3 * rstd * g[tid + 96] + bb[tid + 96];
    }
}

// Flash-style single-pass MHA with nq=1, H=8, dh=16 over nkeys streaming keys.
// Each warp owns keys t = warp + i*NW (nkeys % (NW*4) == 0 required).
// Lane group (lane>>2) owns head h; each lane owns 4 dims of that head.
// red scratch: [NW*128] o-partials, then [NW*8] m, [NW*8] l  (1152 floats).
// out[128] = softmax(q·K / 4) @ V
template<bool USE_MASK, bool EXTRA_KV>
__device__ void attention(const float4* __restrict__ Kb, const float4* __restrict__ Vb,
                          int nkeys, const int* __restrict__ maskb,
                          const float* __restrict__ q,
                          const float* __restrict__ kex, const float* __restrict__ vex,
                          float* __restrict__ out, float* __restrict__ red, int tid)
{
    const int lane = tid & 31, warp = tid >> 5;
    const int h = lane >> 2;
    float* red_o = red;                 // NW * 128
    float* red_m = red + NW * 128;      // NW * 8
    float* red_l = red_m + NW * 8;      // NW * 8

    float4 q4 = ((const float4*)q)[lane];
    float m = -INFINITY, l = 0.0f;
    float4 o = make_float4(0.f, 0.f, 0.f, 0.f);

    for (int t0 = warp; t0 < nkeys; t0 += NW * 4) {
        float4 kk[4], vv[4];
        int mk[4];
#pragma unroll
        for (int u = 0; u < 4; u++) {
            int t = t0 + u * NW;
            kk[u] = Kb[(size_t)t * 32 + lane];
            vv[u] = Vb[(size_t)t * 32 + lane];
            if (USE_MASK) mk[u] = maskb[t];
        }
#pragma unroll
        for (int u = 0; u < 4; u++) {
            float s = kk[u].x * q4.x + kk[u].y * q4.y + kk[u].z * q4.z + kk[u].w * q4.w;
            s += __shfl_xor_sync(0xffffffffu, s, 1);
            s += __shfl_xor_sync(0xffffffffu, s, 2);
            s *= 0.25f;                           // 1/sqrt(dh=16)
            if (USE_MASK && mk[u] == 1) s = -1e9f;
            float mn = fmaxf(m, s);
            float sc = __expf(m - mn);
            float p  = __expf(s - mn);
            l = l * sc + p;
            o.x = o.x * sc + p * vv[u].x;
            o.y = o.y * sc + p * vv[u].y;
            o.z = o.z * sc + p * vv[u].z;
            o.w = o.w * sc + p * vv[u].w;
            m = mn;
        }
    }

    if (EXTRA_KV && warp == 0) {   // appended key index nkeys (from smem)
        float4 kk = ((const float4*)kex)[lane];
        float4 vv = ((const float4*)vex)[lane];
        float s = kk.x * q4.x + kk.y * q4.y + kk.z * q4.z + kk.w * q4.w;
        s += __shfl_xor_sync(0xffffffffu, s, 1);
        s += __shfl_xor_sync(0xffffffffu, s, 2);
        s *= 0.25f;
        float mn = fmaxf(m, s);
        float sc = __expf(m - mn);
        float p  = __expf(s - mn);
        l = l * sc + p;
        o.x = o.x * sc + p * vv.x;
        o.y = o.y * sc + p * vv.y;
        o.z = o.z * sc + p * vv.z;
        o.w = o.w * sc + p * vv.w;
        m = mn;
    }

    // write per-warp partials
    ((float4*)(red_o + warp * 128))[lane] = o;
    if ((lane & 3) == 0) {
        red_m[warp * 8 + h] = m;
        red_l[warp * 8 + h] = l;
    }
    __syncthreads();

    // merge across warps: thread d < 128 handles output dim d (head d>>4)
    if (tid < 128) {
        int hh = tid >> 4;
        float M = -INFINITY;
#pragma unroll
        for (int w = 0; w < NW; w++) M = fmaxf(M, red_m[w * 8 + hh]);
        float L = 0.f, O = 0.f;
#pragma unroll
        for (int w = 0; w < NW; w++) {
            float sc = __expf(red_m[w * 8 + hh] - M);
            L += red_l[w * 8 + hh] * sc;
            O += red_o[w * 128 + tid] * sc;
        }
        out[tid] = O / L;
    }
    __syncthreads();
}

__global__ void __launch_bounds__(NT, 4)
ARD_67765993997201_kernel(const float* __restrict__ ht_in,
                          const float* __restrict__ key,
                          const float* __restrict__ value,
                          const int*   __restrict__ mask,
                          const float* __restrict__ kprev,
                          const float* __restrict__ vprev,
                          const float* __restrict__ W,
                          const float* __restrict__ bvec,
                          const float* __restrict__ ln_g,
                          const float* __restrict__ ln_b,
                          float* __restrict__ out)
{
    const int b = blockIdx.x;
    const int tid = threadIdx.x;

    __shared__ float ht[128], qb[128], kb[128], vb[128], tmp[128], att[128];
    __shared__ float red[NW * 128 + NW * 8 * 2];

    if (tid < 128) ht[tid] = ht_in[(size_t)b * DD + tid];
    __syncthreads();

    // q, k, v projections (disjoint outputs -> one sync after all three)
    gemv128(W + 0 * DD * DD, bvec + 0 * DD, ht, qb, tid);
    gemv128(W + 1 * DD * DD, bvec + 1 * DD, ht, kb, tid);
    gemv128(W + 2 * DD * DD, bvec + 2 * DD, ht, vb, tid);
    __syncthreads();

    // Attention 1: over [kprev ; k], [vprev ; v], no mask
    {
        const float4* Kp = (const float4*)kprev + (size_t)b * TPREV * 32;
        const float4* Vp = (const float4*)vprev + (size_t)b * TPREV * 32;
        attention<false, true>(Kp, Vp, TPREV, nullptr, qb, kb, vb, att, red, tid);
    }

    gemv128(W + 3 * DD * DD, bvec + 3 * DD, att, tmp, tid);
    __syncthreads();
    if (tid < 128) ht[tid] += tmp[tid];
    __syncthreads();
    layernorm128(ht, ln_g + 0 * DD, ln_b + 0 * DD, tid);
    __syncthreads();

    // query projection
    gemv128(W + 4 * DD * DD, bvec + 4 * DD, ht, qb, tid);
    __syncthreads();

    // Attention 2: over key/value with mask
    {
        const float4* Kb2 = (const float4*)key   + (size_t)b * NN * 32;
        const float4* Vb2 = (const float4*)value + (size_t)b * NN * 32;
        attention<true, false>(Kb2, Vb2, NN, mask + (size_t)b * NN,
                               qb, nullptr, nullptr, att, red, tid);
    }

    gemv128(W + 5 * DD * DD, bvec + 5 * DD, att, tmp, tid);
    __syncthreads();
    if (tid < 128) ht[tid] += tmp[tid];
    __syncthreads();
    layernorm128(ht, ln_g + 1 * DD, ln_b + 1 * DD, tid);
    __syncthreads();

    // FFN: ht += W6 @ relu(W7 @ ht + b7) + b6
    gemv128(W + 7 * DD * DD, bvec + 7 * DD, ht, tmp, tid);
    __syncthreads();
    if (tid < 128) tmp[tid] = fmaxf(tmp[tid], 0.0f);
    __syncthreads();
    gemv128(W + 6 * DD * DD, bvec + 6 * DD, tmp, qb, tid);
    __syncthreads();
    if (tid < 128) ht[tid] += qb[tid];
    __syncthreads();
    layernorm128(ht, ln_g + 2 * DD, ln_b + 2 * DD, tid);
    __syncthreads();

    if (tid < 128) out[(size_t)b * DD + tid] = ht[tid];
}

extern "C" void kernel_launch(void* const* d_in, const int* in_sizes, int n_in,
                              void* d_out, int out_size)
{
    const float* ht    = (const float*)d_in[0];
    const float* key   = (const float*)d_in[1];
    const float* value = (const float*)d_in[2];
    const int*   mask  = (const int*)  d_in[3];
    const float* kprev = (const float*)d_in[4];
    const float* vprev = (const float*)d_in[5];
    const float* W     = (const float*)d_in[6];
    const float* bvec  = (const float*)d_in[7];
    const float* ln_g  = (const float*)d_in[8];
    const float* ln_b  = (const float*)d_in[9];
    float* out = (float*)d_out;

    ARD_67765993997201_kernel<<<BB, NT>>>(ht, key, value, mask, kprev, vprev,
                                          W, bvec, ln_g, ln_b, out);
}

// round 3
// speedup vs baseline: 1.4371x; 1.4371x over previous
#include <cuda_runtime.h>
#include <math.h>
#include <stdint.h>

#define BB     512
#define NN     4096
#define DD     128
#define HH     8
#define TPREV  2048
#define NW     8       // warps per CTA
#define NT     256

__device__ __forceinline__ float warpReduceSum(float v) {
#pragma unroll
    for (int o = 16; o > 0; o >>= 1) v += __shfl_xor_sync(0xffffffffu, v, o);
    return v;
}

// out[j] = sum_i x[i]*W[j*128+i] + bias[j]. All 256 threads.
__device__ void gemv128(const float* __restrict__ W, const float* __restrict__ bias,
                        const float* __restrict__ x, float* __restrict__ out, int tid)
{
    int warp = tid >> 5, lane = tid & 31;
    float4 xv = ((const float4*)x)[lane];
#pragma unroll
    for (int jj = 0; jj < 16; jj++) {
        int j = warp * 16 + jj;
        float4 wv = ((const float4*)(W + j * DD))[lane];
        float p = wv.x * xv.x + wv.y * xv.y + wv.z * xv.z + wv.w * xv.w;
        p = warpReduceSum(p);
        if (lane == 0) out[j] = p + bias[j];
    }
}

__device__ void layernorm128(float* __restrict__ x, const float* __restrict__ g,
                             const float* __restrict__ bb, int tid)
{
    if (tid < 32) {
        float v0 = x[tid], v1 = x[tid + 32], v2 = x[tid + 64], v3 = x[tid + 96];
        float s = warpReduceSum(v0 + v1 + v2 + v3);
        float mu = s * (1.0f / 128.0f);
        float d0 = v0 - mu, d1 = v1 - mu, d2 = v2 - mu, d3 = v3 - mu;
        float sq = warpReduceSum(d0 * d0 + d1 * d1 + d2 * d2 + d3 * d3);
        float rstd = rsqrtf(sq * (1.0f / 128.0f) + 1e-5f);
        x[tid]      = d0 * rstd * g[tid]      + bb[tid];
        x[tid + 32] = d1 * rstd * g[tid + 32] + bb[tid + 32];
        x[tid + 64] = d2 * rstd * g[tid + 64] + bb[tid + 64];
        x[tid + 96] = d3 * rstd * g[tid + 96] + bb[tid + 96];
    }
}

__device__ __forceinline__ void online_update(const float4& kk, const float4& vv,
                                              const float4& q4, float& m, float& l,
                                              float4& o)
{
    float s = kk.x * q4.x + kk.y * q4.y + kk.z * q4.z + kk.w * q4.w;
    s += __shfl_xor_sync(0xffffffffu, s, 1);
    s += __shfl_xor_sync(0xffffffffu, s, 2);
    s *= 0.25f;                               // 1/sqrt(dh=16)
    float mn = fmaxf(m, s);
    float sc = __expf(m - mn);
    float p  = __expf(s - mn);
    l = l * sc + p;
    o.x = o.x * sc + p * vv.x;
    o.y = o.y * sc + p * vv.y;
    o.z = o.z * sc + p * vv.z;
    o.w = o.w * sc + p * vv.w;
    m = mn;
}

// Cross-warp merge of online-softmax partials. red layout: [NW*128] o, [NW*8] m, [NW*8] l.
__device__ void merge_partials(float m, float l, float4 o, float* __restrict__ red,
                               float* __restrict__ out, int tid)
{
    const int lane = tid & 31, warp = tid >> 5;
    float* red_o = red;
    float* red_m = red + NW * 128;
    float* red_l = red_m + NW * 8;

    ((float4*)(red_o + warp * 128))[lane] = o;
    if ((lane & 3) == 0) {
        red_m[warp * 8 + (lane >> 2)] = m;
        red_l[warp * 8 + (lane >> 2)] = l;
    }
    __syncthreads();

    if (tid < 128) {
        int hh = tid >> 4;
        float M = -INFINITY;
#pragma unroll
        for (int w = 0; w < NW; w++) M = fmaxf(M, red_m[w * 8 + hh]);
        float L = 0.f, O = 0.f;
#pragma unroll
        for (int w = 0; w < NW; w++) {
            float sc = __expf(red_m[w * 8 + hh] - M);
            L += red_l[w * 8 + hh] * sc;
            O += red_o[w * 128 + tid] * sc;
        }
        out[tid] = O / L;
    }
    __syncthreads();
}

// Attention 1: unmasked stream over nkeys, plus one extra appended K/V from smem.
__device__ void attention_plain(const float4* __restrict__ Kb, const float4* __restrict__ Vb,
                                int nkeys, const float* __restrict__ q,
                                const float* __restrict__ kex, const float* __restrict__ vex,
                                float* __restrict__ out, float* __restrict__ red, int tid)
{
    const int lane = tid & 31, warp = tid >> 5;
    float4 q4 = ((const float4*)q)[lane];
    float m = -INFINITY, l = 0.0f;
    float4 o = make_float4(0.f, 0.f, 0.f, 0.f);

    for (int t0 = warp; t0 < nkeys; t0 += NW * 4) {
        float4 kk[4], vv[4];
#pragma unroll
        for (int u = 0; u < 4; u++) {
            int t = t0 + u * NW;
            kk[u] = Kb[(size_t)t * 32 + lane];
            vv[u] = Vb[(size_t)t * 32 + lane];
        }
#pragma unroll
        for (int u = 0; u < 4; u++) online_update(kk[u], vv[u], q4, m, l, o);
    }

    if (warp == 0) {  // appended current-step k/v
        float4 kk = ((const float4*)kex)[lane];
        float4 vv = ((const float4*)vex)[lane];
        online_update(kk, vv, q4, m, l, o);
    }
    merge_partials(m, l, o, red, out, tid);
}

// Attention 2: masked. mbits[t>>5] bit (t&31) == 1 means key t is masked (skipped).
// Warp w owns contiguous keys [w*(nkeys/NW), (w+1)*(nkeys/NW)).
__device__ void attention_masked(const float4* __restrict__ Kb, const float4* __restrict__ Vb,
                                 int nkeys, const unsigned int* __restrict__ mbits,
                                 const float* __restrict__ q,
                                 float* __restrict__ out, float* __restrict__ red, int tid)
{
    const int lane = tid & 31, warp = tid >> 5;
    float4 q4 = ((const float4*)q)[lane];
    float m = -INFINITY, l = 0.0f;
    float4 o = make_float4(0.f, 0.f, 0.f, 0.f);

    const int per_warp = nkeys / NW;           // 512
    const int start = warp * per_warp;

    for (int base = start; base < start + per_warp; base += 32) {
        unsigned int word = mbits[base >> 5];
        if (word == 0xffffffffu) continue;     // all 32 masked (rare)
#pragma unroll
        for (int j0 = 0; j0 < 32; j0 += 4) {
            float4 kk[4], vv[4];
            bool act[4];
#pragma unroll
            for (int u = 0; u < 4; u++) {
                act[u] = ((word >> (j0 + u)) & 1u) == 0u;
                if (act[u]) {
                    int t = base + j0 + u;
                    kk[u] = Kb[(size_t)t * 32 + lane];
                    vv[u] = Vb[(size_t)t * 32 + lane];
                }
            }
#pragma unroll
            for (int u = 0; u < 4; u++)
                if (act[u]) online_update(kk[u], vv[u], q4, m, l, o);
        }
    }
    merge_partials(m, l, o, red, out, tid);
}

__global__ void __launch_bounds__(NT, 4)
ARD_67765993997201_kernel(const float* __restrict__ ht_in,
                          const float* __restrict__ key,
                          const float* __restrict__ value,
                          const int*   __restrict__ mask,
                          const float* __restrict__ kprev,
                          const float* __restrict__ vprev,
                          const float* __restrict__ W,
                          const float* __restrict__ bvec,
                          const float* __restrict__ ln_g,
                          const float* __restrict__ ln_b,
                          float* __restrict__ out)
{
    const int b = blockIdx.x;
    const int tid = threadIdx.x;
    const int lane = tid & 31, warp = tid >> 5;

    __shared__ float ht[128], qb[128], kb[128], vb[128], tmp[128], att[128];
    __shared__ float red[NW * 128 + NW * 8 * 2];
    __shared__ unsigned int mbits[NN / 32];        // 128 words = 512 B

    if (tid < 128) ht[tid] = ht_in[(size_t)b * DD + tid];

    // Build mask bitset early so its DRAM latency hides under attn-1.
    {
        const int* mb = mask + (size_t)b * NN;
#pragma unroll
        for (int r = 0; r < NN / (NW * 32); r++) {      // 16 rounds
            int widx = r * NW + warp;
            unsigned int bal = __ballot_sync(0xffffffffu, mb[widx * 32 + lane] == 1);
            if (lane == 0) mbits[widx] = bal;
        }
    }
    __syncthreads();

    // q, k, v projections
    gemv128(W + 0 * DD * DD, bvec + 0 * DD, ht, qb, tid);
    gemv128(W + 1 * DD * DD, bvec + 1 * DD, ht, kb, tid);
    gemv128(W + 2 * DD * DD, bvec + 2 * DD, ht, vb, tid);
    __syncthreads();

    // Attention 1: over [kprev ; k], [vprev ; v], no mask
    attention_plain((const float4*)kprev + (size_t)b * TPREV * 32,
                    (const float4*)vprev + (size_t)b * TPREV * 32,
                    TPREV, qb, kb, vb, att, red, tid);

    gemv128(W + 3 * DD * DD, bvec + 3 * DD, att, tmp, tid);
    __syncthreads();
    if (tid < 128) ht[tid] += tmp[tid];
    __syncthreads();
    layernorm128(ht, ln_g + 0 * DD, ln_b + 0 * DD, tid);
    __syncthreads();

    // query projection
    gemv128(W + 4 * DD * DD, bvec + 4 * DD, ht, qb, tid);
    __syncthreads();

    // Attention 2: over key/value with mask-skip
    attention_masked((const float4*)key   + (size_t)b * NN * 32,
                     (const float4*)value + (size_t)b * NN * 32,
                     NN, mbits, qb, att, red, tid);

    gemv128(W + 5 * DD * DD, bvec + 5 * DD, att, tmp, tid);
    __syncthreads();
    if (tid < 128) ht[tid] += tmp[tid];
    __syncthreads();
    layernorm128(ht, ln_g + 1 * DD, ln_b + 1 * DD, tid);
    __syncthreads();

    // FFN: ht += W6 @ relu(W7 @ ht + b7) + b6
    gemv128(W + 7 * DD * DD, bvec + 7 * DD, ht, tmp, tid);
    __syncthreads();
    if (tid < 128) tmp[tid] = fmaxf(tmp[tid], 0.0f);
    __syncthreads();
    gemv128(W + 6 * DD * DD, bvec + 6 * DD, tmp, qb, tid);
    __syncthreads();
    if (tid < 128) ht[tid] += qb[tid];
    __syncthreads();
    layernorm128(ht, ln_g + 2 * DD, ln_b + 2 * DD, tid);
    __syncthreads();

    if (tid < 128) out[(size_t)b * DD + tid] = ht[tid];
}

extern "C" void kernel_launch(void* const* d_in, const int* in_sizes, int n_in,
                              void* d_out, int out_size)
{
    const float* ht    = (const float*)d_in[0];
    const float* key   = (const float*)d_in[1];
    const float* value = (const float*)d_in[2];
    const int*   mask  = (const int*)  d_in[3];
    const float* kprev = (const float*)d_in[4];
    const float* vprev = (const float*)d_in[5];
    const float* W     = (const float*)d_in[6];
    const float* bvec  = (const float*)d_in[7];
    const float* ln_g  = (const float*)d_in[8];
    const float* ln_b  = (const float*)d_in[9];
    float* out = (float*)d_out;

    ARD_67765993997201_kernel<<<BB, NT>>>(ht, key, value, mask, kprev, vprev,
                                          W, bvec, ln_g, ln_b, out);
}